// round 9
// baseline (speedup 1.0000x reference)
#include <cuda_runtime.h>
#include <cstdint>

// Problem shapes (fixed by the dataset)
constexpr int Bdim = 8;
constexpr int T    = 512;
constexpr int D    = 1024;
constexpr int E    = 64;

// Tiling: CTA 128x64, warp tile 32x32, 8 warps (4M x 2N), occupancy 2
constexpr int BM = 128;
constexpr int BN = 64;
constexpr int BK = 32;
constexpr int STAGES = 3;
constexpr int NSEG = 2 * (D / BK);   // 64 segments (2 experts x 32 K-slabs)
constexpr int THREADS = 256;

constexpr int AS_STRIDE = BK + 4;    // 36
constexpr int BS_STRIDE = BN + 8;    // 72
constexpr int A_STAGE = BM * AS_STRIDE;   // 4608 floats
constexpr int B_STAGE = BK * BS_STRIDE;   // 2304 floats
constexpr int SMEM_BYTES = STAGES * (A_STAGE + B_STAGE) * 4;  // 82944

// RNA-rounded copy of x (tf32-exact; raw LDS feed == RNA rounding for A)
__device__ float g_x_round[(size_t)Bdim * T * D];

__device__ __forceinline__ void cp16(float* smem_ptr, const float* gmem_ptr) {
    uint32_t s = (uint32_t)__cvta_generic_to_shared(smem_ptr);
    asm volatile("cp.async.cg.shared.global [%0], [%1], 16;" :: "r"(s), "l"(gmem_ptr));
}
__device__ __forceinline__ uint32_t f2tf32(float f) {
    uint32_t r;
    asm("cvt.rna.tf32.f32 %0, %1;" : "=r"(r) : "f"(f));
    return r;
}
__device__ __forceinline__ void mma_tf32(float* c, const uint32_t* a, const uint32_t* b) {
    asm volatile(
        "mma.sync.aligned.m16n8k8.row.col.f32.tf32.tf32.f32 "
        "{%0,%1,%2,%3}, {%4,%5,%6,%7}, {%8,%9}, {%0,%1,%2,%3};\n"
        : "+f"(c[0]), "+f"(c[1]), "+f"(c[2]), "+f"(c[3])
        : "r"(a[0]), "r"(a[1]), "r"(a[2]), "r"(a[3]), "r"(b[0]), "r"(b[1]));
}

// idx dtype auto-detect (proven in R3): int32 unless all high words zero.
__device__ __forceinline__ int load_expert_idx(const void* idx_raw, int pos) {
    const int* p32 = (const int*)idx_raw;
    bool is64 = true;
    #pragma unroll
    for (int j = 1; j < 16; j += 2) is64 &= (p32[j] == 0);
    int e = is64 ? p32[2 * pos] : p32[pos];
    return min(max(e, 0), E - 1);
}

// Pre-kernel: RNA-round x once
__global__ void round_x_kernel(const float* __restrict__ x) {
    const int n4 = (Bdim * T * D) / 4;
    const float4* src = (const float4*)x;
    float4* dst = (float4*)g_x_round;
    for (int i = blockIdx.x * blockDim.x + threadIdx.x; i < n4; i += gridDim.x * blockDim.x) {
        float4 v = src[i];
        v.x = __uint_as_float(f2tf32(v.x));
        v.y = __uint_as_float(f2tf32(v.y));
        v.z = __uint_as_float(f2tf32(v.z));
        v.w = __uint_as_float(f2tf32(v.w));
        dst[i] = v;
    }
}

extern __shared__ float smem[];

__global__ void __launch_bounds__(THREADS, 2)
expertbank_kernel(const float* __restrict__ w,
                  const float* __restrict__ Wb,
                  const float* __restrict__ bb,
                  const void*  __restrict__ idx,
                  float* __restrict__ out)
{
    const int tn = blockIdx.x;   // N tile (0..15)
    const int tm = blockIdx.y;   // M tile (0..3)
    const int b  = blockIdx.z;   // batch

    const int tid  = threadIdx.x;
    const int lane = tid & 31;
    const int warp = tid >> 5;
    const int wm = warp & 3;     // warp row (4 in M)
    const int wn = warp >> 2;    // warp col (2 in N)

    const float* xblk = g_x_round + ((size_t)b * T + (size_t)tm * BM) * D;

    const int e0 = load_expert_idx(idx, b * 2 + 0);
    const int e1 = load_expert_idx(idx, b * 2 + 1);
    const float w0 = w[b * 2 + 0];
    const float w1 = w[b * 2 + 1];
    const float* Wp[2] = { Wb + (size_t)e0 * D * D + (size_t)tn * BN,
                           Wb + (size_t)e1 * D * D + (size_t)tn * BN };

    float* As0 = smem;                    // STAGES x [BM][AS_STRIDE]
    float* Bs0 = smem + STAGES * A_STAGE; // STAGES x [BK][BS_STRIDE]

    float out_acc[2][4][4];
    float acc[2][4][4];
    #pragma unroll
    for (int mi = 0; mi < 2; ++mi)
        #pragma unroll
        for (int ni = 0; ni < 4; ++ni)
            #pragma unroll
            for (int j = 0; j < 4; ++j) {
                out_acc[mi][ni][j] = 0.f;
                acc[mi][ni][j] = 0.f;
            }

    // fragment base indices
    const int ar = wm * 32 + (lane >> 2);       // A row within tile
    const int bc = wn * 32 + (lane >> 2);       // B col within tile

    auto load_ab = [&](int s, int stage) {
        float* Ad = As0 + stage * A_STAGE;
        const float* Ag = xblk + (s & 31) * BK;
        #pragma unroll
        for (int i = 0; i < 4; ++i) {
            int lin = tid + i * THREADS;          // 0..1023
            int m  = lin >> 3;                    // 128 rows
            int kv = (lin & 7) << 2;              // 8 float4 per row
            cp16(Ad + m * AS_STRIDE + kv, Ag + (size_t)m * D + kv);
        }
        float* Bd = Bs0 + stage * B_STAGE;
        const float* Bg = Wp[s >> 5] + (size_t)(s & 31) * BK * D;
        #pragma unroll
        for (int i = 0; i < 2; ++i) {
            int lin = tid + i * THREADS;          // 0..511
            int k  = lin >> 4;                    // 32 rows
            int nv = (lin & 15) << 2;             // 16 float4 per row
            cp16(Bd + k * BS_STRIDE + nv, Bg + (size_t)k * D + nv);
        }
        asm volatile("cp.async.commit_group;" ::: "memory");
    };

    // prologue: stages 0 and 1 in flight
    load_ab(0, 0);
    load_ab(1, 1);

    for (int s = 0; s < NSEG; ++s) {
        if (s == NSEG - 1)
            asm volatile("cp.async.wait_group 0;" ::: "memory");
        else
            asm volatile("cp.async.wait_group 1;" ::: "memory");
        __syncthreads();

        if (s + 2 < NSEG) load_ab(s + 2, (s + 2) % STAGES);

        const float* Ab = As0 + (s % STAGES) * A_STAGE;
        const float* Bb = Bs0 + (s % STAGES) * B_STAGE;

        #pragma unroll
        for (int kk = 0; kk < BK / 8; ++kk) {
            const int c = kk * 8 + (lane & 3);
            uint32_t af[2][4];
            #pragma unroll
            for (int mi = 0; mi < 2; ++mi) {
                const float* A0 = Ab + (ar + mi * 16) * AS_STRIDE + c;
                af[mi][0] = __float_as_uint(A0[0]);
                af[mi][1] = __float_as_uint(A0[8 * AS_STRIDE]);
                af[mi][2] = __float_as_uint(A0[4]);
                af[mi][3] = __float_as_uint(A0[8 * AS_STRIDE + 4]);
            }
            uint32_t bf[4][2];
            #pragma unroll
            for (int ni = 0; ni < 4; ++ni) {
                const float* B0 = Bb + c * BS_STRIDE + bc + ni * 8;
                bf[ni][0] = __float_as_uint(B0[0]);
                bf[ni][1] = __float_as_uint(B0[4 * BS_STRIDE]);
            }
            #pragma unroll
            for (int mi = 0; mi < 2; ++mi)
                #pragma unroll
                for (int ni = 0; ni < 4; ++ni)
                    mma_tf32(acc[mi][ni], af[mi], bf[ni]);
        }

        // expert-0 boundary: fold into out_acc, reset acc (thread-local, no sync)
        if (s == (NSEG / 2) - 1) {
            const float* bp = bb + (size_t)e0 * D + (size_t)tn * BN;
            #pragma unroll
            for (int mi = 0; mi < 2; ++mi)
                #pragma unroll
                for (int ni = 0; ni < 4; ++ni) {
                    int col = wn * 32 + ni * 8 + (lane & 3) * 2;
                    float b0v = bp[col], b1v = bp[col + 1];
                    out_acc[mi][ni][0] += w0 * fmaxf(acc[mi][ni][0] + b0v, 0.f);
                    out_acc[mi][ni][1] += w0 * fmaxf(acc[mi][ni][1] + b1v, 0.f);
                    out_acc[mi][ni][2] += w0 * fmaxf(acc[mi][ni][2] + b0v, 0.f);
                    out_acc[mi][ni][3] += w0 * fmaxf(acc[mi][ni][3] + b1v, 0.f);
                    acc[mi][ni][0] = 0.f; acc[mi][ni][1] = 0.f;
                    acc[mi][ni][2] = 0.f; acc[mi][ni][3] = 0.f;
                }
        }
    }

    // expert-1 fold + store
    {
        const float* bp = bb + (size_t)e1 * D + (size_t)tn * BN;
        float* ob = out + ((size_t)b * T + (size_t)tm * BM) * D + (size_t)tn * BN;
        #pragma unroll
        for (int mi = 0; mi < 2; ++mi)
            #pragma unroll
            for (int ni = 0; ni < 4; ++ni) {
                int col = wn * 32 + ni * 8 + (lane & 3) * 2;
                float b0v = bp[col], b1v = bp[col + 1];
                float v00 = out_acc[mi][ni][0] + w1 * fmaxf(acc[mi][ni][0] + b0v, 0.f);
                float v01 = out_acc[mi][ni][1] + w1 * fmaxf(acc[mi][ni][1] + b1v, 0.f);
                float v10 = out_acc[mi][ni][2] + w1 * fmaxf(acc[mi][ni][2] + b0v, 0.f);
                float v11 = out_acc[mi][ni][3] + w1 * fmaxf(acc[mi][ni][3] + b1v, 0.f);
                int r0 = wm * 32 + mi * 16 + (lane >> 2);
                *reinterpret_cast<float2*>(&ob[(size_t)r0 * D + col]) = make_float2(v00, v01);
                *reinterpret_cast<float2*>(&ob[(size_t)(r0 + 8) * D + col]) = make_float2(v10, v11);
            }
    }
}

extern "C" void kernel_launch(void* const* d_in, const int* in_sizes, int n_in,
                              void* d_out, int out_size) {
    const float* x   = (const float*)d_in[0];
    const float* w   = (const float*)d_in[1];
    const float* Wb  = (const float*)d_in[2];
    const float* bb  = (const float*)d_in[3];
    const void*  idx = (const void*)d_in[4];
    float* out = (float*)d_out;

    round_x_kernel<<<2048, 256>>>(x);

    cudaFuncSetAttribute(expertbank_kernel,
                         cudaFuncAttributeMaxDynamicSharedMemorySize, SMEM_BYTES);
    dim3 grid(D / BN, T / BM, Bdim);  // (16, 4, 8) = 512 blocks
    expertbank_kernel<<<grid, THREADS, SMEM_BYTES>>>(w, Wb, bb, idx, out);
}

// round 13
// speedup vs baseline: 1.1481x; 1.1481x over previous
#include <cuda_runtime.h>
#include <cstdint>

// Problem shapes (fixed by the dataset)
constexpr int Bdim = 8;
constexpr int T    = 512;
constexpr int D    = 1024;
constexpr int E    = 64;

// Tiling: CTA 128x128, warp tile 32x64, BK=64, 3-stage cp.async pipeline
constexpr int BM = 128;
constexpr int BN = 128;
constexpr int BK = 64;
constexpr int STAGES = 3;
constexpr int NSEG = 2 * (D / BK);   // 32 segments (2 experts x 16 slabs)
constexpr int THREADS = 256;         // 8 warps: 4 in M x 2 in N

constexpr int AS_STRIDE = BK + 4;    // 68
constexpr int BS_STRIDE = BN + 8;    // 136
constexpr int A_STAGE = BM * AS_STRIDE;   // 8704 floats
constexpr int B_STAGE = BK * BS_STRIDE;   // 8704 floats
constexpr int SMEM_BYTES = STAGES * (A_STAGE + B_STAGE) * 4;  // 208896

// RNA-rounded copy of x (tf32-exact; raw LDS feed == RNA rounding for A)
__device__ float g_x_round[(size_t)Bdim * T * D];

__device__ __forceinline__ void cp16(float* smem_ptr, const float* gmem_ptr) {
    uint32_t s = (uint32_t)__cvta_generic_to_shared(smem_ptr);
    asm volatile("cp.async.cg.shared.global [%0], [%1], 16;" :: "r"(s), "l"(gmem_ptr));
}
__device__ __forceinline__ uint32_t f2tf32(float f) {
    uint32_t r;
    asm("cvt.rna.tf32.f32 %0, %1;" : "=r"(r) : "f"(f));
    return r;
}
__device__ __forceinline__ void mma_tf32(float* c, const uint32_t* a, const uint32_t* b) {
    asm volatile(
        "mma.sync.aligned.m16n8k8.row.col.f32.tf32.tf32.f32 "
        "{%0,%1,%2,%3}, {%4,%5,%6,%7}, {%8,%9}, {%0,%1,%2,%3};\n"
        : "+f"(c[0]), "+f"(c[1]), "+f"(c[2]), "+f"(c[3])
        : "r"(a[0]), "r"(a[1]), "r"(a[2]), "r"(a[3]), "r"(b[0]), "r"(b[1]));
}

// idx dtype auto-detect (proven in R3): int32 unless all high words zero.
__device__ __forceinline__ int load_expert_idx(const void* idx_raw, int pos) {
    const int* p32 = (const int*)idx_raw;
    bool is64 = true;
    #pragma unroll
    for (int j = 1; j < 16; j += 2) is64 &= (p32[j] == 0);
    int e = is64 ? p32[2 * pos] : p32[pos];
    return min(max(e, 0), E - 1);
}

// Pre-kernel: RNA-round x once
__global__ void round_x_kernel(const float* __restrict__ x) {
    const int n4 = (Bdim * T * D) / 4;
    const float4* src = (const float4*)x;
    float4* dst = (float4*)g_x_round;
    for (int i = blockIdx.x * blockDim.x + threadIdx.x; i < n4; i += gridDim.x * blockDim.x) {
        float4 v = src[i];
        v.x = __uint_as_float(f2tf32(v.x));
        v.y = __uint_as_float(f2tf32(v.y));
        v.z = __uint_as_float(f2tf32(v.z));
        v.w = __uint_as_float(f2tf32(v.w));
        dst[i] = v;
    }
}

extern __shared__ float smem[];

__global__ void __launch_bounds__(THREADS, 1)
expertbank_kernel(const float* __restrict__ w,
                  const float* __restrict__ Wb,
                  const float* __restrict__ bb,
                  const void*  __restrict__ idx,
                  float* __restrict__ out)
{
    const int tn = blockIdx.x;   // N tile (0..7)
    const int tm = blockIdx.y;   // M tile (0..3)
    const int b  = blockIdx.z;   // batch

    const int tid  = threadIdx.x;
    const int lane = tid & 31;
    const int warp = tid >> 5;
    const int wm = warp & 3;     // warp row (4 in M)
    const int wn = warp >> 2;    // warp col (2 in N)

    const float* xblk = g_x_round + ((size_t)b * T + (size_t)tm * BM) * D;

    const int e0 = load_expert_idx(idx, b * 2 + 0);
    const int e1 = load_expert_idx(idx, b * 2 + 1);
    const float w0 = w[b * 2 + 0];
    const float w1 = w[b * 2 + 1];
    const float* Wp[2] = { Wb + (size_t)e0 * D * D + (size_t)tn * BN,
                           Wb + (size_t)e1 * D * D + (size_t)tn * BN };

    float* As0 = smem;                    // STAGES x [BM][AS_STRIDE]
    float* Bs0 = smem + STAGES * A_STAGE; // STAGES x [BK][BS_STRIDE]

    float out_acc[2][8][4];
    float acc[2][8][4];
    #pragma unroll
    for (int mi = 0; mi < 2; ++mi)
        #pragma unroll
        for (int ni = 0; ni < 8; ++ni)
            #pragma unroll
            for (int j = 0; j < 4; ++j) {
                out_acc[mi][ni][j] = 0.f;
                acc[mi][ni][j] = 0.f;
            }

    const int ar = wm * 32 + (lane >> 2);   // A fragment base row
    const int bc = wn * 64 + (lane >> 2);   // B fragment base col

    auto load_ab = [&](int s, int stage) {
        float* Ad = As0 + stage * A_STAGE;
        const float* Ag = xblk + (s & 15) * BK;
        #pragma unroll
        for (int i = 0; i < 8; ++i) {
            int lin = tid + i * THREADS;          // 0..2047
            int m  = lin >> 4;                    // 128 rows, 16 float4/row
            int kv = (lin & 15) << 2;
            cp16(Ad + m * AS_STRIDE + kv, Ag + (size_t)m * D + kv);
        }
        float* Bd = Bs0 + stage * B_STAGE;
        const float* Bg = Wp[s >> 4] + (size_t)(s & 15) * BK * D;
        #pragma unroll
        for (int i = 0; i < 8; ++i) {
            int lin = tid + i * THREADS;          // 0..2047
            int k  = lin >> 5;                    // 64 rows, 32 float4/row
            int nv = (lin & 31) << 2;
            cp16(Bd + k * BS_STRIDE + nv, Bg + (size_t)k * D + nv);
        }
        asm volatile("cp.async.commit_group;" ::: "memory");
    };

    // prologue: stages 0 and 1 in flight
    load_ab(0, 0);
    load_ab(1, 1);

    for (int s = 0; s < NSEG; ++s) {
        if (s >= NSEG - 2)
            asm volatile("cp.async.wait_group 0;" ::: "memory");
        else
            asm volatile("cp.async.wait_group 1;" ::: "memory");
        __syncthreads();

        if (s + 2 < NSEG) load_ab(s + 2, (s + 2) % STAGES);

        const float* Ab = As0 + (s % STAGES) * A_STAGE;
        const float* Bb = Bs0 + (s % STAGES) * B_STAGE;

        // fragment double-buffer across the 8 kk steps
        uint32_t af[2][2][4];   // [buf][mi][4]
        uint32_t bf[2][8][2];   // [buf][ni][2]

        auto ldfrag = [&](int kk, int fb) {
            const int c = kk * 8 + (lane & 3);
            #pragma unroll
            for (int mi = 0; mi < 2; ++mi) {
                const float* A0 = Ab + (ar + mi * 16) * AS_STRIDE + c;
                af[fb][mi][0] = __float_as_uint(A0[0]);
                af[fb][mi][1] = __float_as_uint(A0[8 * AS_STRIDE]);
                af[fb][mi][2] = __float_as_uint(A0[4]);
                af[fb][mi][3] = __float_as_uint(A0[8 * AS_STRIDE + 4]);
            }
            #pragma unroll
            for (int ni = 0; ni < 8; ++ni) {
                const float* B0 = Bb + c * BS_STRIDE + bc + ni * 8;
                bf[fb][ni][0] = __float_as_uint(B0[0]);
                bf[fb][ni][1] = __float_as_uint(B0[4 * BS_STRIDE]);
            }
        };

        ldfrag(0, 0);
        #pragma unroll
        for (int kk = 0; kk < BK / 8; ++kk) {
            const int cur = kk & 1;
            if (kk + 1 < BK / 8) ldfrag(kk + 1, cur ^ 1);
            #pragma unroll
            for (int mi = 0; mi < 2; ++mi)
                #pragma unroll
                for (int ni = 0; ni < 8; ++ni)
                    mma_tf32(acc[mi][ni], af[cur][mi], bf[cur][ni]);
        }

        // expert-0 boundary: fold into out_acc, reset acc (thread-local)
        if (s == (NSEG / 2) - 1) {
            const float* bp = bb + (size_t)e0 * D + (size_t)tn * BN;
            #pragma unroll
            for (int mi = 0; mi < 2; ++mi)
                #pragma unroll
                for (int ni = 0; ni < 8; ++ni) {
                    int col = wn * 64 + ni * 8 + (lane & 3) * 2;
                    float b0v = bp[col], b1v = bp[col + 1];
                    out_acc[mi][ni][0] = w0 * fmaxf(acc[mi][ni][0] + b0v, 0.f);
                    out_acc[mi][ni][1] = w0 * fmaxf(acc[mi][ni][1] + b1v, 0.f);
                    out_acc[mi][ni][2] = w0 * fmaxf(acc[mi][ni][2] + b0v, 0.f);
                    out_acc[mi][ni][3] = w0 * fmaxf(acc[mi][ni][3] + b1v, 0.f);
                    acc[mi][ni][0] = 0.f; acc[mi][ni][1] = 0.f;
                    acc[mi][ni][2] = 0.f; acc[mi][ni][3] = 0.f;
                }
        }
    }

    // expert-1 fold + store
    {
        const float* bp = bb + (size_t)e1 * D + (size_t)tn * BN;
        float* ob = out + ((size_t)b * T + (size_t)tm * BM) * D + (size_t)tn * BN;
        #pragma unroll
        for (int mi = 0; mi < 2; ++mi)
            #pragma unroll
            for (int ni = 0; ni < 8; ++ni) {
                int col = wn * 64 + ni * 8 + (lane & 3) * 2;
                float b0v = bp[col], b1v = bp[col + 1];
                float v00 = out_acc[mi][ni][0] + w1 * fmaxf(acc[mi][ni][0] + b0v, 0.f);
                float v01 = out_acc[mi][ni][1] + w1 * fmaxf(acc[mi][ni][1] + b1v, 0.f);
                float v10 = out_acc[mi][ni][2] + w1 * fmaxf(acc[mi][ni][2] + b0v, 0.f);
                float v11 = out_acc[mi][ni][3] + w1 * fmaxf(acc[mi][ni][3] + b1v, 0.f);
                int r0 = wm * 32 + mi * 16 + (lane >> 2);
                *reinterpret_cast<float2*>(&ob[(size_t)r0 * D + col]) = make_float2(v00, v01);
                *reinterpret_cast<float2*>(&ob[(size_t)(r0 + 8) * D + col]) = make_float2(v10, v11);
            }
    }
}

extern "C" void kernel_launch(void* const* d_in, const int* in_sizes, int n_in,
                              void* d_out, int out_size) {
    const float* x   = (const float*)d_in[0];
    const float* w   = (const float*)d_in[1];
    const float* Wb  = (const float*)d_in[2];
    const float* bb  = (const float*)d_in[3];
    const void*  idx = (const void*)d_in[4];
    float* out = (float*)d_out;

    round_x_kernel<<<2048, 256>>>(x);

    cudaFuncSetAttribute(expertbank_kernel,
                         cudaFuncAttributeMaxDynamicSharedMemorySize, SMEM_BYTES);
    dim3 grid(D / BN, T / BM, Bdim);  // (8, 4, 8) = 256 blocks
    expertbank_kernel<<<grid, THREADS, SMEM_BYTES>>>(w, Wb, bb, idx, out);
}